// round 8
// baseline (speedup 1.0000x reference)
#include <cuda_runtime.h>
#include <cstdint>

#define E_TOT  43234
#define NTILE  1352          // 32-entity tiles
#define NTHR   256

// prep output (global), then copied into the 64KB constant bank
__device__ float4 g_head_f4[4096];       // [(b*64+q)*2 + {0,1}] = -re quad, -im quad
__constant__ float4 c_head[4096];        // 64KB, LDC/ULDC path
__device__ int g_ctr[4 * 32];            // per-bgroup steal counters, 128B apart

// ---------- f32x2 packed helpers (sm_103a) ----------
static __device__ __forceinline__ unsigned long long addx2(unsigned long long a, unsigned long long b) {
    unsigned long long r; asm("add.rn.f32x2 %0, %1, %2;" : "=l"(r) : "l"(a), "l"(b)); return r;
}
static __device__ __forceinline__ unsigned long long mulx2(unsigned long long a, unsigned long long b) {
    unsigned long long r; asm("mul.rn.f32x2 %0, %1, %2;" : "=l"(r) : "l"(a), "l"(b)); return r;
}
static __device__ __forceinline__ unsigned long long fmax2(unsigned long long a, unsigned long long b, unsigned long long c) {
    unsigned long long r; asm("fma.rn.f32x2 %0, %1, %2, %3;" : "=l"(r) : "l"(a), "l"(b), "l"(c)); return r;
}
static __device__ __forceinline__ void unpack2(unsigned long long v, float& lo, float& hi) {
    asm("mov.b64 {%0, %1}, %2;" : "=f"(lo), "=f"(hi) : "l"(v));
}
static __device__ __forceinline__ float sqrt_approx(float x) {
    float r; asm("sqrt.approx.f32 %0, %1;" : "=f"(r) : "f"(x)); return r;
}

// ---------- prep: rotate head, negate; layout (b, q)-major quads; reset counters ----------
__global__ void prep_kernel(const float* __restrict__ head, const float* __restrict__ rel) {
    int b = blockIdx.x, d = threadIdx.x;
    if (b == 0 && d < 4) g_ctr[d * 32] = 0;
    float re_h = head[b * 512 + d];
    float im_h = head[b * 512 + 256 + d];
    float phase = rel[b * 256 + d] * 100.53096491487338f;  // rel * 32*pi
    float s, c; sincosf(phase, &s, &c);
    float re_rot = re_h * c - im_h * s;
    float im_rot = re_h * s + im_h * c;
    int q = d >> 2, j = d & 3;
    float* G = reinterpret_cast<float*>(g_head_f4);
    G[((b * 64 + q) * 2) * 4 + j]     = -re_rot;
    G[((b * 64 + q) * 2 + 1) * 4 + j] = -im_rot;
}

// ---------- main: lane=entity, warp=8 b (bgroup=blockIdx.y); warp-private cp.async ring ----------
__global__ void __launch_bounds__(NTHR, 3)
dist_kernel(const float* __restrict__ ent, float* __restrict__ out) {
    extern __shared__ char smem[];                   // 8 warps * 8KB
    const int wid  = threadIdx.x >> 5;
    const int lane = threadIdx.x & 31;
    const int bg   = blockIdx.y;
    char*    wbase = smem + wid * 8192;              // [buf(2)][qq(4)][part(2)][lane(32)] * 16B
    const uint32_t wsh = (uint32_t)__cvta_generic_to_shared(wbase) + lane * 16;
    int* ctr = &g_ctr[bg * 32];
    // constant head, uniform-indexed: Hc[bb*128 + q*2 + {0,1}]
    const ulonglong2* Hc = reinterpret_cast<const ulonglong2*>(c_head) + bg * 1024;

    int tile = 0;
    if (lane == 0) tile = atomicAdd(ctr, 1);
    tile = __shfl_sync(0xffffffffu, tile, 0);

    while (tile < NTILE) {
        int e0 = tile * 32;
        if (e0 > E_TOT - 32) e0 = E_TOT - 32;        // clamped tail: overlap rewrites identical values
        const char* ebase = reinterpret_cast<const char*>(ent) + (size_t)(e0 + lane) * 2048;

        // stage chunk 0 (q=0..3) into buf 0
#pragma unroll
        for (int part = 0; part < 2; part++)
#pragma unroll
            for (int qq = 0; qq < 4; qq++)
                asm volatile("cp.async.cg.shared.global [%0], [%1], 16;"
                             :: "r"(wsh + qq * 1024 + part * 512),
                                "l"(ebase + part * 1024 + qq * 16));
        asm volatile("cp.async.commit_group;");

        // grab next tile early (latency hidden under chunk-0 fill + compute)
        int ntile = 0;
        if (lane == 0) ntile = atomicAdd(ctr, 1);
        ntile = __shfl_sync(0xffffffffu, ntile, 0);

        float acc[8] = {0, 0, 0, 0, 0, 0, 0, 0};
        int cur = 0;
        for (int c = 0; c < 16; c++) {
            if (c < 15) {   // stage chunk c+1 into the other buffer, then let chunk c land
                const char* s = ebase + (c + 1) * 64;
                const uint32_t d0 = wsh + ((cur ^ 1) * 4096);
#pragma unroll
                for (int part = 0; part < 2; part++)
#pragma unroll
                    for (int qq = 0; qq < 4; qq++)
                        asm volatile("cp.async.cg.shared.global [%0], [%1], 16;"
                                     :: "r"(d0 + qq * 1024 + part * 512),
                                        "l"(s + part * 1024 + qq * 16));
                asm volatile("cp.async.commit_group;");
                asm volatile("cp.async.wait_group 1;" ::: "memory");
            } else {
                asm volatile("cp.async.wait_group 0;" ::: "memory");
            }

            const char* sb = wbase + cur * 4096 + lane * 16;
#pragma unroll
            for (int qq = 0; qq < 4; qq++) {
                // this lane's entity quads (conflict-free LDS.128)
                ulonglong2 er = *reinterpret_cast<const ulonglong2*>(sb + qq * 1024);
                ulonglong2 ei = *reinterpret_cast<const ulonglong2*>(sb + qq * 1024 + 512);
                const int q = c * 4 + qq;
#pragma unroll
                for (int bb = 0; bb < 8; bb++) {
                    // uniform constant-port loads (no L1)
                    ulonglong2 hr = Hc[bb * 128 + q * 2];
                    ulonglong2 hi = Hc[bb * 128 + q * 2 + 1];
                    unsigned long long a0 = addx2(er.x, hr.x);   // t_re - rot_re pairs
                    unsigned long long a1 = addx2(er.y, hr.y);
                    unsigned long long c0 = addx2(ei.x, hi.x);
                    unsigned long long c1 = addx2(ei.y, hi.y);
                    unsigned long long p0 = fmax2(c0, c0, mulx2(a0, a0));
                    unsigned long long p1 = fmax2(c1, c1, mulx2(a1, a1));
                    float x0, x1, y0, y1;
                    unpack2(p0, x0, x1);
                    unpack2(p1, y0, y1);
                    acc[bb] += (sqrt_approx(x0) + sqrt_approx(x1)) +
                               (sqrt_approx(y0) + sqrt_approx(y1));
                }
            }
            cur ^= 1;
        }

#pragma unroll
        for (int bb = 0; bb < 8; bb++)
            out[(size_t)(bg * 8 + bb) * E_TOT + e0 + lane] = 6.0f - acc[bb];

        tile = ntile;
    }
}

extern "C" void kernel_launch(void* const* d_in, const int* in_sizes, int n_in,
                              void* d_out, int out_size) {
    const float* head = (const float*)d_in[0];   // (32, 512)
    const float* rel  = (const float*)d_in[1];   // (32, 256)
    const float* ent  = (const float*)d_in[2];   // (43234, 512)
    float* out = (float*)d_out;                  // (32, 43234)

    prep_kernel<<<32, 256>>>(head, rel);

    void* gsrc = nullptr;
    cudaGetSymbolAddress(&gsrc, g_head_f4);
    cudaMemcpyToSymbolAsync(c_head, gsrc, 4096 * sizeof(float4), 0,
                            cudaMemcpyDeviceToDevice, 0);

    cudaFuncSetAttribute(dist_kernel, cudaFuncAttributeMaxDynamicSharedMemorySize, 65536);
    dist_kernel<<<dim3(111, 4), NTHR, 65536>>>(ent, out);
}

// round 9
// speedup vs baseline: 4.1826x; 4.1826x over previous
#include <cuda_runtime.h>
#include <cstdint>

#define E_TOT  43234
#define ET     8
#define NWTILE 5405            // ceil(E_TOT/8)
#define NBLK   296             // 2 CTA/SM * 148
#define NTHR   256

// Rotated+NEGATED head, lane-transposed: g_head[dp*32 + b] = {-re(2dp),-re(2dp+1),-im(2dp),-im(2dp+1)}
__device__ float4 g_head[128 * 32];
__device__ int g_ctr;

// ---------- f32x2 packed helpers (sm_103a) ----------
static __device__ __forceinline__ unsigned long long addx2(unsigned long long a, unsigned long long b) {
    unsigned long long r; asm("add.rn.f32x2 %0, %1, %2;" : "=l"(r) : "l"(a), "l"(b)); return r;
}
static __device__ __forceinline__ unsigned long long mulx2(unsigned long long a, unsigned long long b) {
    unsigned long long r; asm("mul.rn.f32x2 %0, %1, %2;" : "=l"(r) : "l"(a), "l"(b)); return r;
}
static __device__ __forceinline__ unsigned long long fmax2(unsigned long long a, unsigned long long b, unsigned long long c) {
    unsigned long long r; asm("fma.rn.f32x2 %0, %1, %2, %3;" : "=l"(r) : "l"(a), "l"(b), "l"(c)); return r;
}
static __device__ __forceinline__ void unpack2(unsigned long long v, float& lo, float& hi) {
    asm("mov.b64 {%0, %1}, %2;" : "=f"(lo), "=f"(hi) : "l"(v));
}
static __device__ __forceinline__ float sqrt_approx(float x) {
    float r; asm("sqrt.approx.f32 %0, %1;" : "=f"(r) : "f"(x)); return r;
}

// ---------- prep: rotate head, negate + transpose; reset steal counter ----------
__global__ void prep_kernel(const float* __restrict__ head, const float* __restrict__ rel) {
    int b = blockIdx.x, d = threadIdx.x;
    if (b == 0 && d == 0) g_ctr = 0;
    float re_h = head[b * 512 + d];
    float im_h = head[b * 512 + 256 + d];
    float phase = rel[b * 256 + d] * 100.53096491487338f;  // rel * 32*pi
    float s, c; sincosf(phase, &s, &c);
    float re_rot = re_h * c - im_h * s;
    float im_rot = re_h * s + im_h * c;
    int dp = d >> 1, k = d & 1;
    float* base = reinterpret_cast<float*>(&g_head[dp * 32 + b]);
    base[k]     = -re_rot;
    base[2 + k] = -im_rot;
}

// ---------- main: lane = b, warp = 8-entity tile (work-stealing), head table in smem ----------
__global__ void __launch_bounds__(NTHR, 2)
dist_kernel(const float* __restrict__ ent, float* __restrict__ out) {
    extern __shared__ ulonglong2 sh2[];  // [128*32] = 64KB; sh2[dp*32+lane] = {re_pair, im_pair}
    {
        const float4* src = g_head;
        float4* dst = reinterpret_cast<float4*>(sh2);
        for (int i = threadIdx.x; i < 128 * 32; i += NTHR) dst[i] = src[i];
    }
    __syncthreads();

    const int lane = threadIdx.x & 31;
    const ulonglong2* __restrict__ hs = sh2 + lane;

    // work stealing: one tile per grab
    int tile;
    if (lane == 0) tile = atomicAdd(&g_ctr, 1);
    tile = __shfl_sync(0xffffffffu, tile, 0);

    while (tile < NWTILE) {
        int e0 = tile * ET;
        if (e0 > E_TOT - ET) e0 = E_TOT - ET;   // clamped tail: overlap rewrites identical values
        const ulonglong2* __restrict__ base =
            reinterpret_cast<const ulonglong2*>(ent) + (size_t)e0 * 128;
        // entity t: re quad = base[t*128 + q], im quad = base[t*128 + 64 + q]

        // grab next tile early (hides the atomic + shfl latency under the q-loop)
        int ntile;
        if (lane == 0) ntile = atomicAdd(&g_ctr, 1);
        ntile = __shfl_sync(0xffffffffu, ntile, 0);

        float acc[ET];
#pragma unroll
        for (int t = 0; t < ET; t++) acc[t] = 0.0f;

#pragma unroll 2
        for (int q = 0; q < 64; q++) {
            // 16 independent warp-uniform broadcast LDG.128 (MLP=16, L1/L2-resident)
            ulonglong2 re[ET], im[ET];
#pragma unroll
            for (int t = 0; t < ET; t++) {
                re[t] = __ldg(base + t * 128 + q);
                im[t] = __ldg(base + t * 128 + 64 + q);
            }
            // this lane's head quads for d=4q..4q+3: two conflict-free LDS.128
            ulonglong2 h0 = hs[(2 * q) * 32];       // {-re pair d0d1, -im pair d0d1}
            ulonglong2 h1 = hs[(2 * q) * 32 + 32];  // {-re pair d2d3, -im pair d2d3}

#pragma unroll
            for (int t = 0; t < ET; t++) {
                unsigned long long a0 = addx2(re[t].x, h0.x);
                unsigned long long c0 = addx2(im[t].x, h0.y);
                unsigned long long a1 = addx2(re[t].y, h1.x);
                unsigned long long c1 = addx2(im[t].y, h1.y);
                unsigned long long p0 = fmax2(c0, c0, mulx2(a0, a0));
                unsigned long long p1 = fmax2(c1, c1, mulx2(a1, a1));
                float x0, x1, y0, y1;
                unpack2(p0, x0, x1);
                unpack2(p1, y0, y1);
                acc[t] += (sqrt_approx(x0) + sqrt_approx(x1)) +
                          (sqrt_approx(y0) + sqrt_approx(y1));
            }
        }

        // 8 results -> two 16B stores (e0 multiple of 8 except clamped tail: still 8-float aligned? 
        // E_TOT-8 = 43226, not 16B-aligned -> use float2 stores, always 8B-aligned)
        float2* op = reinterpret_cast<float2*>(out + (size_t)lane * E_TOT + e0);
        op[0] = make_float2(6.0f - acc[0], 6.0f - acc[1]);
        op[1] = make_float2(6.0f - acc[2], 6.0f - acc[3]);
        op[2] = make_float2(6.0f - acc[4], 6.0f - acc[5]);
        op[3] = make_float2(6.0f - acc[6], 6.0f - acc[7]);

        tile = ntile;
    }
}

extern "C" void kernel_launch(void* const* d_in, const int* in_sizes, int n_in,
                              void* d_out, int out_size) {
    const float* head = (const float*)d_in[0];   // (32, 512)
    const float* rel  = (const float*)d_in[1];   // (32, 256)
    const float* ent  = (const float*)d_in[2];   // (43234, 512)
    float* out = (float*)d_out;                  // (32, 43234)

    cudaFuncSetAttribute(dist_kernel, cudaFuncAttributeMaxDynamicSharedMemorySize, 65536);

    prep_kernel<<<32, 256>>>(head, rel);
    dist_kernel<<<NBLK, NTHR, 65536>>>(ent, out);
}